// round 15
// baseline (speedup 1.0000x reference)
#include <cuda_runtime.h>
#include <cuda_bf16.h>
#include <cstdint>
#include <math.h>

#define NTOK 6144
#define DMODEL 256
#define NHEAD 8
#define DKH 32
#define NLAYER 2
#define NVOCAB 1024
#define LSEQ 96
#define NBATCH 64

typedef __nv_bfloat16 bf16;
typedef __nv_bfloat162 bf162;

// ---------------------------------------------------------------------------
// Scratch.  Packed operands are 128B-aligned (cp.async.bulk requires 16B
// alignment of global source).  qkv stays row-major (consumed by attention).
// ---------------------------------------------------------------------------
__device__ float g_x  [NTOK * DMODEL];
__device__ __align__(128) bf16  g_qkvb[NTOK * 3 * DMODEL];
__device__ __align__(128) bf16  g_xn [NTOK * DMODEL];
__device__ __align__(128) bf16  g_att[NTOK * DMODEL];
__device__ __align__(128) bf16  g_mid[NTOK * 4 * DMODEL];
__device__ __align__(128) bf16  g_xb [NTOK * DMODEL];
__device__ __align__(128) bf16 g_wqkv[NLAYER * DMODEL * 3 * DMODEL];
__device__ __align__(128) bf16 g_wo  [NLAYER * DMODEL * DMODEL];
__device__ __align__(128) bf16 g_wf1 [NLAYER * DMODEL * 4 * DMODEL];
__device__ __align__(128) bf16 g_wf2 [NLAYER * 4 * DMODEL * DMODEL];
__device__ __align__(128) bf16 g_wgen[DMODEL * NVOCAB];

// ---------------------------------------------------------------------------
// helpers
// ---------------------------------------------------------------------------
__device__ __forceinline__ unsigned pk2(float a, float b)
{
    bf162 t = __floats2bfloat162_rn(a, b);
    return *(unsigned*)&t;
}

__device__ __forceinline__ void mma_bf16(float* c, unsigned a0, unsigned a1,
                                         unsigned a2, unsigned a3,
                                         unsigned b0, unsigned b1)
{
    asm volatile(
        "mma.sync.aligned.m16n8k16.row.col.f32.bf16.bf16.f32 "
        "{%0,%1,%2,%3}, {%4,%5,%6,%7}, {%8,%9}, {%0,%1,%2,%3};"
        : "+f"(c[0]), "+f"(c[1]), "+f"(c[2]), "+f"(c[3])
        : "r"(a0), "r"(a1), "r"(a2), "r"(a3), "r"(b0), "r"(b1));
}

__device__ __forceinline__ void ldsm4u(unsigned& r0, unsigned& r1,
                                       unsigned& r2, unsigned& r3, unsigned addr)
{
    asm volatile("ldmatrix.sync.aligned.m8n8.x4.shared.b16 {%0,%1,%2,%3}, [%4];"
                 : "=r"(r0), "=r"(r1), "=r"(r2), "=r"(r3) : "r"(addr));
}

__device__ __forceinline__ void ldsm4tu(unsigned& r0, unsigned& r1,
                                        unsigned& r2, unsigned& r3, unsigned addr)
{
    asm volatile("ldmatrix.sync.aligned.m8n8.x4.trans.shared.b16 {%0,%1,%2,%3}, [%4];"
                 : "=r"(r0), "=r"(r1), "=r"(r2), "=r"(r3) : "r"(addr));
}

__device__ __forceinline__ void ldsm4(unsigned& r0, unsigned& r1,
                                      unsigned& r2, unsigned& r3, const void* p)
{
    ldsm4u(r0, r1, r2, r3, (unsigned)__cvta_generic_to_shared(p));
}

__device__ __forceinline__ void bulk_g2s(unsigned dst, const void* src, unsigned mba)
{
    asm volatile(
        "cp.async.bulk.shared::cluster.global.mbarrier::complete_tx::bytes "
        "[%0], [%1], %2, [%3];"
        :: "r"(dst), "l"(src), "r"(4096u), "r"(mba) : "memory");
}

__device__ __forceinline__ void mb_init(unsigned addr)
{
    asm volatile("mbarrier.init.shared.b64 [%0], %1;" :: "r"(addr), "r"(1u) : "memory");
}

__device__ __forceinline__ void mb_expect(unsigned addr, unsigned bytes)
{
    asm volatile("mbarrier.arrive.expect_tx.shared.b64 _, [%0], %1;"
                 :: "r"(addr), "r"(bytes) : "memory");
}

// bounded parity wait (no hang on bugs)
__device__ __forceinline__ void mb_wait(unsigned addr, unsigned parity)
{
    unsigned done = 0;
    for (int it = 0; it < (1 << 22) && !done; it++) {
        asm volatile(
            "{\n\t.reg .pred p;\n\t"
            "mbarrier.try_wait.parity.acquire.cta.shared::cta.b64 p, [%1], %2, 0x989680;\n\t"
            "selp.b32 %0, 1, 0, p;\n\t}"
            : "=r"(done) : "r"(addr), "r"(parity) : "memory");
    }
}

// ---------------------------------------------------------------------------
// Packed layouts (elem offsets into bf16 arrays).  Tk = K/16.
// A block (activations): 128 rows x 16 kcols = 2048 elems (4KB).
//   granule pos = 2r + (h ^ ((r>>2)&1)),  h = (col>>3)&1
// B block (weights): 16 krows x 128 ncols = 2048 elems (4KB).
//   granule pos = 16*kr + (c16 ^ (kr&7)),  c16 = (n>>3)&15
// Both conflict-free for the R9 ldmatrix phase patterns.
// ---------------------------------------------------------------------------
__device__ __forceinline__ size_t apack(int row, int col, int Tk)
{
    int bidx = (row >> 7) * Tk + (col >> 4);
    int r = row & 127;
    int h = (col >> 3) & 1;
    int pos = r * 2 + (h ^ ((r >> 2) & 1));
    return (size_t)bidx * 2048 + pos * 8 + (col & 7);
}

__device__ __forceinline__ size_t bpack(int k, int n, int Tk)
{
    int bidx = (n >> 7) * Tk + (k >> 4);
    int kr = k & 15;
    int c16 = (n >> 3) & 15;
    int pos = kr * 16 + (c16 ^ (kr & 7));
    return (size_t)bidx * 2048 + pos * 8 + (n & 7);
}

// ---------------------------------------------------------------------------
// Weight conversion fp32 [NL][K][N] -> packed bf16 B-blocks (one launch).
// FIX (R14 bug): layer index must be split out of k and applied as a flat
// per-layer destination offset; bpack is per-layer.
// ---------------------------------------------------------------------------
__global__ void cvt5_k(const float4* __restrict__ q,  const float4* __restrict__ o,
                       const float4* __restrict__ f1, const float4* __restrict__ f2,
                       const float4* __restrict__ gw,
                       bf16* __restrict__ qd,  bf16* __restrict__ od,
                       bf16* __restrict__ f1d, bf16* __restrict__ f2d,
                       bf16* __restrict__ gd)
{
    int i = blockIdx.x * 256 + threadIdx.x;
    const float4* s; bf16* d; int j = i; int N, Tk, K;
    if (j < 98304)                    { s = q;  d = qd;  N = 768;  Tk = 16; K = 256;  }
    else if ((j -= 98304)  < 32768)   { s = o;  d = od;  N = 256;  Tk = 16; K = 256;  }
    else if ((j -= 32768)  < 131072)  { s = f1; d = f1d; N = 1024; Tk = 16; K = 256;  }
    else if ((j -= 131072) < 131072)  { s = f2; d = f2d; N = 256;  Tk = 64; K = 1024; }
    else { j -= 131072;                 s = gw; d = gd;  N = 1024; Tk = 16; K = 256;  }
    int n4 = N >> 2;
    int kt = j / n4, n = (j - kt * n4) * 4;
    int l = kt / K;                 // layer index
    int k = kt - l * K;             // k within layer
    d += (size_t)l * K * N;         // flat per-layer base
    float4 v = s[j];
    uint2 u;
    u.x = pk2(v.x, v.y);
    u.y = pk2(v.z, v.w);
    *(uint2*)(d + bpack(k, n, Tk)) = u;
}

// ---------------------------------------------------------------------------
// Embedding
// ---------------------------------------------------------------------------
__global__ void embed_k(const int* __restrict__ tok, const int* __restrict__ pos,
                        const float* __restrict__ ve, const float* __restrict__ ce,
                        const float* __restrict__ pe, float* __restrict__ x)
{
    int n = blockIdx.x;
    int d = threadIdx.x;
    int p = pos[n];
    x[n * DMODEL + d] = ce[(p % 3) * DMODEL + d]
                      + pe[(p / 3) * DMODEL + d]
                      + ve[tok[n] * DMODEL + d];
}

// ---------------------------------------------------------------------------
// LayerNorm: one warp per row, fp32 in, PACKED bf16 out (Tk=16)
// ---------------------------------------------------------------------------
__global__ void ln_k(const float* __restrict__ x, const float* __restrict__ s,
                     const float* __restrict__ b, bf16* __restrict__ y)
{
    int row  = blockIdx.x * 8 + (threadIdx.x >> 5);
    int lane = threadIdx.x & 31;
    const float4* xr = (const float4*)(x + (size_t)row * DMODEL);
    float4 v0 = xr[lane];
    float4 v1 = xr[lane + 32];

    float sum = v0.x + v0.y + v0.z + v0.w + v1.x + v1.y + v1.z + v1.w;
    #pragma unroll
    for (int o = 16; o > 0; o >>= 1) sum += __shfl_xor_sync(0xffffffffu, sum, o);
    float mu = sum * (1.0f / DMODEL);

    float d0x=v0.x-mu, d0y=v0.y-mu, d0z=v0.z-mu, d0w=v0.w-mu;
    float d1x=v1.x-mu, d1y=v1.y-mu, d1z=v1.z-mu, d1w=v1.w-mu;
    float sq = d0x*d0x+d0y*d0y+d0z*d0z+d0w*d0w + d1x*d1x+d1y*d1y+d1z*d1z+d1w*d1w;
    #pragma unroll
    for (int o = 16; o > 0; o >>= 1) sq += __shfl_xor_sync(0xffffffffu, sq, o);
    float rs = rsqrtf(sq * (1.0f / DMODEL) + 1e-5f);

    const float4* sv = (const float4*)s;
    const float4* bv = (const float4*)b;
    float4 s0 = sv[lane], s1 = sv[lane + 32];
    float4 b0 = bv[lane], b1 = bv[lane + 32];
    uint2 u0, u1;
    u0.x = pk2(d0x*rs*s0.x + b0.x, d0y*rs*s0.y + b0.y);
    u0.y = pk2(d0z*rs*s0.z + b0.z, d0w*rs*s0.w + b0.w);
    u1.x = pk2(d1x*rs*s1.x + b1.x, d1y*rs*s1.y + b1.y);
    u1.y = pk2(d1z*rs*s1.z + b1.z, d1w*rs*s1.w + b1.w);
    *(uint2*)(y + apack(row, lane * 4, 16))        = u0;
    *(uint2*)(y + apack(row, (lane + 32) * 4, 16)) = u1;
}

// ---------------------------------------------------------------------------
// bf16 tensor-core attention (R9 compute), output written PACKED (Tk=16)
// ---------------------------------------------------------------------------
__global__ __launch_bounds__(128)
void attn_k(const bf16* __restrict__ qkv, bf16* __restrict__ o)
{
    __shared__ bf16 sm[13824];
    __shared__ float zpart[4][96];
    __shared__ float zinv[96];

    int bh = blockIdx.x;
    int b = bh >> 3, h = bh & 7;
    int base = b * LSEQ;
    int tid  = threadIdx.x;
    int lane = tid & 31, wid = tid >> 5;
    int g = lane >> 2, lt = lane & 3;
    int ltile = lane >> 3, lr = lane & 7;
    int a_roff = (ltile & 1) * 8 + lr;
    int a_koff = (ltile >> 1) * 8;

    const bf16* Qg = qkv + (size_t)base * 768 + h * DKH;
    const bf16* Kg = Qg + DMODEL;
    const bf16* Vg = Qg + 2 * DMODEL;

    unsigned vreg[6][2];
    int d0 = 8 * wid;
    #pragma unroll
    for (int kc = 0; kc < 6; kc++) {
        int k0 = 16 * kc + 2 * lt;
        unsigned lo0 = *(const unsigned short*)(Vg + (size_t)k0       * 768 + d0 + g);
        unsigned hi0 = *(const unsigned short*)(Vg + (size_t)(k0 + 1) * 768 + d0 + g);
        unsigned lo1 = *(const unsigned short*)(Vg + (size_t)(k0 + 8) * 768 + d0 + g);
        unsigned hi1 = *(const unsigned short*)(Vg + (size_t)(k0 + 9) * 768 + d0 + g);
        vreg[kc][0] = lo0 | (hi0 << 16);
        vreg[kc][1] = lo1 | (hi1 << 16);
    }

    for (int idx = tid; idx < 96 * 4; idx += 128) {
        int r = idx >> 2, q = idx & 3;
        int kc = q >> 1, off8 = (q & 1) * 8;
        uint4 qv = *(const uint4*)(Qg + (size_t)r * 768 + q * 8);
        uint4 kv = *(const uint4*)(Kg + (size_t)r * 768 + q * 8);
        *(uint4*)&sm[kc * 2304 + r * 24 + off8] = qv;
        *(uint4*)&sm[4608 + kc * 2304 + r * 24 + off8] = kv;
    }
    __syncthreads();

    float acc[6][3][4];
    #pragma unroll
    for (int i = 0; i < 6; i++)
        #pragma unroll
        for (int j = 0; j < 3; j++)
            #pragma unroll
            for (int v = 0; v < 4; v++) acc[i][j][v] = 0.0f;

    int J0 = 3 * wid;
    #pragma unroll
    for (int kc = 0; kc < 2; kc++) {
        unsigned s0, s1, s2, s3, t0, t1, t2, t3;
        ldsm4(s0, s1, s2, s3,
              &sm[4608 + kc * 2304 + (24 * wid + a_roff) * 24 + a_koff]);
        ldsm4(t0, t1, t2, t3,
              &sm[4608 + kc * 2304 + (24 * wid + 16 + a_roff) * 24 + a_koff]);
        (void)t1; (void)t3;

        #pragma unroll
        for (int i = 0; i < 6; i++) {
            if (8 * J0 > 16 * i + 15) continue;
            unsigned a0, a1, a2, a3;
            ldsm4(a0, a1, a2, a3, &sm[kc * 2304 + (16 * i + a_roff) * 24 + a_koff]);
            if (8 * (J0 + 0) <= 16 * i + 15) mma_bf16(acc[i][0], a0, a1, a2, a3, s0, s2);
            if (8 * (J0 + 1) <= 16 * i + 15) mma_bf16(acc[i][1], a0, a1, a2, a3, s1, s3);
            if (8 * (J0 + 2) <= 16 * i + 15) mma_bf16(acc[i][2], a0, a1, a2, a3, t0, t2);
        }
    }
    __syncthreads();

    float zp[12];
    #pragma unroll
    for (int m = 0; m < 12; m++) zp[m] = 0.0f;
    const float invs = 0.17677669529663687f;

    #pragma unroll
    for (int i = 0; i < 6; i++) {
        int r0 = 16 * i + g, r1 = r0 + 8;
        #pragma unroll
        for (int jl = 0; jl < 3; jl++) {
            int J = J0 + jl;
            if (8 * J > 16 * i + 15) continue;
            int c = 8 * J + 2 * lt;
            float w0 = (c     <= r0) ? __expf(fminf(fmaxf(acc[i][jl][0] * invs, -5.0f), 5.0f)) : 0.0f;
            float w1 = (c + 1 <= r0) ? __expf(fminf(fmaxf(acc[i][jl][1] * invs, -5.0f), 5.0f)) : 0.0f;
            float w2 = (c     <= r1) ? __expf(fminf(fmaxf(acc[i][jl][2] * invs, -5.0f), 5.0f)) : 0.0f;
            float w3 = (c + 1 <= r1) ? __expf(fminf(fmaxf(acc[i][jl][3] * invs, -5.0f), 5.0f)) : 0.0f;
            zp[2 * i]     += w0 + w1;
            zp[2 * i + 1] += w2 + w3;
            int col = (J & 1) * 8 + 2 * lt;
            *(unsigned*)&sm[(J >> 1) * 2304 + r0 * 24 + col] = pk2(w0, w1);
            *(unsigned*)&sm[(J >> 1) * 2304 + r1 * 24 + col] = pk2(w2, w3);
        }
    }
    #pragma unroll
    for (int off = 1; off <= 2; off <<= 1)
        #pragma unroll
        for (int m = 0; m < 12; m++)
            zp[m] += __shfl_xor_sync(0xffffffffu, zp[m], off);
    if (lt == 0) {
        #pragma unroll
        for (int i = 0; i < 6; i++) {
            zpart[wid][16 * i + g]     = zp[2 * i];
            zpart[wid][16 * i + 8 + g] = zp[2 * i + 1];
        }
    }
    __syncthreads();
    if (tid < 96)
        zinv[tid] = 1.0f / (zpart[0][tid] + zpart[1][tid] + zpart[2][tid] + zpart[3][tid]);
    __syncthreads();

    float oacc[6][4];
    #pragma unroll
    for (int i = 0; i < 6; i++)
        #pragma unroll
        for (int v = 0; v < 4; v++) oacc[i][v] = 0.0f;

    #pragma unroll
    for (int i = 0; i < 6; i++) {
        #pragma unroll
        for (int kc = 0; kc < 6; kc++) {
            if (kc > i) break;
            unsigned a0, a1, a2, a3;
            ldsm4(a0, a1, a2, a3, &sm[kc * 2304 + (16 * i + a_roff) * 24 + a_koff]);
            mma_bf16(oacc[i], a0, a1, a2, a3, vreg[kc][0], vreg[kc][1]);
        }
    }

    #pragma unroll
    for (int i = 0; i < 6; i++) {
        int r0 = 16 * i + g, r1 = r0 + 8;
        float zi0 = zinv[r0], zi1 = zinv[r1];
        unsigned u0 = pk2(oacc[i][0] * zi0, oacc[i][1] * zi0);
        unsigned u1 = pk2(oacc[i][2] * zi1, oacc[i][3] * zi1);
        int col = h * DKH + d0 + 2 * lt;
        *(unsigned*)(o + apack(base + r0, col, 16)) = u0;
        *(unsigned*)(o + apack(base + r1, col, 16)) = u1;
    }
}

// ---------------------------------------------------------------------------
// bf16 GEMM on packed tiles: cp.async.bulk pipeline (4 stages x 8KB),
// mbarrier expect_tx completion, R9 fragment compute (8 warps, 32x64).
// OP: 0 bias, 1 bias+relu, 2 bias+residual.
// OUTM: bit0 fp32 C rowmajor, bit1 packed bf16 Cb (TkD), bit2 rowmajor bf16 Cb.
// ---------------------------------------------------------------------------
template<int OP, int OUTM, int TkD>
__global__ __launch_bounds__(256, 2)
void hgemm_k(const bf16* __restrict__ Ap, const bf16* __restrict__ Bp,
             const float* __restrict__ bias, const float* __restrict__ res,
             float* __restrict__ C, bf16* __restrict__ Cb,
             int M, int N, int K)
{
    __shared__ __align__(128) bf16 stg[4][4096];   // per stage: A block | B block
    __shared__ __align__(8) unsigned long long mbar[4];

    int tid  = threadIdx.x;
    int lane = tid & 31, wid = tid >> 5;
    int g = lane >> 2, lt = lane & 3;
    int wm = (wid % 4) * 32;
    int wn = (wid / 4) * 64;
    int m0 = blockIdx.y * 128;
    int n0 = blockIdx.x * 128;

    int ltile = lane >> 3, lr = lane & 7;
    int a_roff = (ltile & 1) * 8 + lr;
    int hA = (ltile >> 1) & 1;
    int b_kr = (ltile & 1) * 8 + lr;
    int b_ch = (ltile >> 1) & 1;

    unsigned stA[4], stB[4], mbu[4];
    #pragma unroll
    for (int s2 = 0; s2 < 4; s2++) {
        stA[s2] = (unsigned)__cvta_generic_to_shared(&stg[s2][0]);
        stB[s2] = stA[s2] + 4096;
        mbu[s2] = (unsigned)__cvta_generic_to_shared(&mbar[s2]);
    }

    if (tid == 0) {
        #pragma unroll
        for (int s2 = 0; s2 < 4; s2++) mb_init(mbu[s2]);
    }
    __syncthreads();

    int T = K >> 4;
    size_t abase = (size_t)blockIdx.y * T * 2048;
    size_t bbase = (size_t)blockIdx.x * T * 2048;

    if (tid == 0) {
        #pragma unroll
        for (int s2 = 0; s2 < 3; s2++) {
            mb_expect(mbu[s2], 8192u);
            bulk_g2s(stA[s2], Ap + abase + (size_t)s2 * 2048, mbu[s2]);
            bulk_g2s(stB[s2], Bp + bbase + (size_t)s2 * 2048, mbu[s2]);
        }
    }

    float acc[2][8][4];
    #pragma unroll
    for (int i = 0; i < 2; i++)
        #pragma unroll
        for (int j = 0; j < 8; j++)
            #pragma unroll
            for (int v = 0; v < 4; v++) acc[i][j][v] = 0.0f;

    for (int kt = 0; kt < T; kt++) {
        int s = kt & 3;
        mb_wait(mbu[s], (kt >> 2) & 1);
        __syncthreads();
        if (tid == 0 && kt + 3 < T) {
            int s3 = (kt + 3) & 3;
            mb_expect(mbu[s3], 8192u);
            bulk_g2s(stA[s3], Ap + abase + (size_t)(kt + 3) * 2048, mbu[s3]);
            bulk_g2s(stB[s3], Bp + bbase + (size_t)(kt + 3) * 2048, mbu[s3]);
        }

        unsigned af[2][4], bf[8][2];
        #pragma unroll
        for (int i = 0; i < 2; i++) {
            int r = wm + 16 * i + a_roff;
            unsigned addr = stA[s] + (unsigned)(r * 32 + ((hA ^ ((r >> 2) & 1)) << 4));
            ldsm4u(af[i][0], af[i][1], af[i][2], af[i][3], addr);
        }
        #pragma unroll
        for (int jp = 0; jp < 4; jp++) {
            int c16 = ((wn + 16 * jp) >> 3) + b_ch;
            unsigned addr = stB[s] + (unsigned)(b_kr * 256 + ((c16 ^ (b_kr & 7)) << 4));
            unsigned r0, r1, r2, r3;
            ldsm4tu(r0, r1, r2, r3, addr);
            bf[2 * jp][0] = r0;  bf[2 * jp][1] = r1;
            bf[2 * jp + 1][0] = r2;  bf[2 * jp + 1][1] = r3;
        }
        #pragma unroll
        for (int i = 0; i < 2; i++)
            #pragma unroll
            for (int j = 0; j < 8; j++)
                mma_bf16(acc[i][j], af[i][0], af[i][1], af[i][2], af[i][3],
                         bf[j][0], bf[j][1]);
    }

    // epilogue
    #pragma unroll
    for (int i = 0; i < 2; i++) {
        int r0 = m0 + wm + 16 * i + g;
        #pragma unroll
        for (int j = 0; j < 8; j++) {
            int c = n0 + wn + 8 * j + 2 * lt;
            float bx = bias[c], by = bias[c + 1];
            float2 v0, v1;
            v0.x = acc[i][j][0] + bx;  v0.y = acc[i][j][1] + by;
            v1.x = acc[i][j][2] + bx;  v1.y = acc[i][j][3] + by;
            if (OP == 1) {
                v0.x = fmaxf(v0.x, 0.0f); v0.y = fmaxf(v0.y, 0.0f);
                v1.x = fmaxf(v1.x, 0.0f); v1.y = fmaxf(v1.y, 0.0f);
            }
            if (OP == 2) {
                float2 r0v = *(const float2*)(res + (size_t)r0 * N + c);
                float2 r1v = *(const float2*)(res + (size_t)(r0 + 8) * N + c);
                v0.x += r0v.x; v0.y += r0v.y;
                v1.x += r1v.x; v1.y += r1v.y;
            }
            if (OUTM & 1) {
                *(float2*)(C + (size_t)r0 * N + c) = v0;
                *(float2*)(C + (size_t)(r0 + 8) * N + c) = v1;
            }
            if (OUTM & 2) {
                *(unsigned*)(Cb + apack(r0, c, TkD))     = pk2(v0.x, v0.y);
                *(unsigned*)(Cb + apack(r0 + 8, c, TkD)) = pk2(v1.x, v1.y);
            }
            if (OUTM & 4) {
                *(unsigned*)(Cb + (size_t)r0 * N + c)       = pk2(v0.x, v0.y);
                *(unsigned*)(Cb + (size_t)(r0 + 8) * N + c) = pk2(v1.x, v1.y);
            }
        }
    }
}

// ---------------------------------------------------------------------------
// In-place log_softmax over VOCAB=1024
// ---------------------------------------------------------------------------
__global__ void lsm_k(float* __restrict__ out)
{
    __shared__ float red[256];
    int n = blockIdx.x, t = threadIdx.x;
    float v[4];
    #pragma unroll
    for (int j = 0; j < 4; j++) v[j] = out[(size_t)n * NVOCAB + t + j * 256];

    float m = fmaxf(fmaxf(v[0], v[1]), fmaxf(v[2], v[3]));
    red[t] = m;
    __syncthreads();
    #pragma unroll
    for (int o = 128; o > 0; o >>= 1) {
        if (t < o) red[t] = fmaxf(red[t], red[t + o]);
        __syncthreads();
    }
    float M = red[0];
    __syncthreads();

    float s = 0.0f;
    #pragma unroll
    for (int j = 0; j < 4; j++) s += __expf(v[j] - M);
    red[t] = s;
    __syncthreads();
    #pragma unroll
    for (int o = 128; o > 0; o >>= 1) {
        if (t < o) red[t] += red[t + o];
        __syncthreads();
    }
    float lse = M + __logf(red[0]);

    #pragma unroll
    for (int j = 0; j < 4; j++)
        out[(size_t)n * NVOCAB + t + j * 256] = v[j] - lse;
}

// ---------------------------------------------------------------------------
// Launch
// ---------------------------------------------------------------------------
extern "C" void kernel_launch(void* const* d_in, const int* in_sizes, int n_in,
                              void* d_out, int out_size)
{
    const int*   tokens    = (const int*)  d_in[0];
    const int*   pos_idx   = (const int*)  d_in[1];
    const float* value_emb = (const float*)d_in[4];
    const float* coord_emb = (const float*)d_in[5];
    const float* pos_emb   = (const float*)d_in[6];
    const float* ln1_s     = (const float*)d_in[7];
    const float* ln1_b     = (const float*)d_in[8];
    const float* W_qkv     = (const float*)d_in[9];
    const float* b_qkv     = (const float*)d_in[10];
    const float* W_o       = (const float*)d_in[11];
    const float* b_o       = (const float*)d_in[12];
    const float* ln2_s     = (const float*)d_in[13];
    const float* ln2_b     = (const float*)d_in[14];
    const float* W_ff1     = (const float*)d_in[15];
    const float* b_ff1     = (const float*)d_in[16];
    const float* W_ff2     = (const float*)d_in[17];
    const float* b_ff2     = (const float*)d_in[18];
    const float* W_gen     = (const float*)d_in[19];
    const float* b_gen     = (const float*)d_in[20];
    float* out = (float*)d_out;

    float *x;
    bf16 *qkvb, *xn, *att, *mid, *xb;
    bf16 *wqkvb, *wob, *wf1b, *wf2b, *wgenb;
    cudaGetSymbolAddress((void**)&x,    g_x);
    cudaGetSymbolAddress((void**)&qkvb, g_qkvb);
    cudaGetSymbolAddress((void**)&xn,   g_xn);
    cudaGetSymbolAddress((void**)&att,  g_att);
    cudaGetSymbolAddress((void**)&mid,  g_mid);
    cudaGetSymbolAddress((void**)&xb,   g_xb);
    cudaGetSymbolAddress((void**)&wqkvb, g_wqkv);
    cudaGetSymbolAddress((void**)&wob,   g_wo);
    cudaGetSymbolAddress((void**)&wf1b,  g_wf1);
    cudaGetSymbolAddress((void**)&wf2b,  g_wf2);
    cudaGetSymbolAddress((void**)&wgenb, g_wgen);

    cvt5_k<<<1792, 256>>>((const float4*)W_qkv, (const float4*)W_o,
                          (const float4*)W_ff1, (const float4*)W_ff2,
                          (const float4*)W_gen,
                          wqkvb, wob, wf1b, wf2b, wgenb);

    embed_k<<<NTOK, DMODEL>>>(tokens, pos_idx, value_emb, coord_emb, pos_emb, x);

    for (int l = 0; l < NLAYER; l++) {
        const bf16* wqkv = wqkvb + (size_t)l * DMODEL * 3 * DMODEL;
        const float* bqkv = b_qkv + (size_t)l * 3 * DMODEL;
        const bf16* wo    = wob   + (size_t)l * DMODEL * DMODEL;
        const float* bo   = b_o   + (size_t)l * DMODEL;
        const bf16* wf1   = wf1b  + (size_t)l * DMODEL * 4 * DMODEL;
        const float* bf1  = b_ff1 + (size_t)l * 4 * DMODEL;
        const bf16* wf2   = wf2b  + (size_t)l * 4 * DMODEL * DMODEL;
        const float* bf2  = b_ff2 + (size_t)l * DMODEL;

        ln_k<<<NTOK / 8, 256>>>(x, ln1_s + l * DMODEL, ln1_b + l * DMODEL, xn);

        { dim3 g(6, 48);
          hgemm_k<0, 4, 16><<<g, 256>>>(xn, wqkv, bqkv, nullptr, nullptr, qkvb,
                                        NTOK, 768, 256); }

        attn_k<<<NBATCH * NHEAD, 128>>>(qkvb, att);

        { dim3 g(2, 48);
          hgemm_k<2, 1, 16><<<g, 256>>>(att, wo, bo, x, x, nullptr,
                                        NTOK, 256, 256); }

        ln_k<<<NTOK / 8, 256>>>(x, ln2_s + l * DMODEL, ln2_b + l * DMODEL, xn);

        { dim3 g(8, 48);
          hgemm_k<1, 2, 64><<<g, 256>>>(xn, wf1, bf1, nullptr, nullptr, mid,
                                        NTOK, 1024, 256); }

        { dim3 g(2, 48);
          hgemm_k<2, 3, 16><<<g, 256>>>(mid, wf2, bf2, x, x, xb,
                                        NTOK, 256, 1024); }
    }

    { dim3 g(8, 48);
      hgemm_k<0, 1, 16><<<g, 256>>>(xb, wgenb, b_gen, nullptr, out, nullptr,
                                    NTOK, 1024, 256); }

    lsm_k<<<NTOK, 256>>>(out);
}

// round 16
// speedup vs baseline: 1.1549x; 1.1549x over previous
#include <cuda_runtime.h>
#include <cuda_bf16.h>
#include <cstdint>
#include <math.h>

#define NTOK 6144
#define DMODEL 256
#define NHEAD 8
#define DKH 32
#define NLAYER 2
#define NVOCAB 1024
#define LSEQ 96
#define NBATCH 64

typedef __nv_bfloat16 bf16;
typedef __nv_bfloat162 bf162;

// ---------------------------------------------------------------------------
// Scratch
// ---------------------------------------------------------------------------
__device__ float g_x  [NTOK * DMODEL];
__device__ bf16  g_qkvb[NTOK * 3 * DMODEL];
__device__ bf16  g_xn [NTOK * DMODEL];
__device__ bf16  g_att[NTOK * DMODEL];
__device__ bf16  g_mid[NTOK * 4 * DMODEL];
__device__ bf16  g_xb [NTOK * DMODEL];
__device__ bf16 g_wqkv[NLAYER * DMODEL * 3 * DMODEL];
__device__ bf16 g_wo  [NLAYER * DMODEL * DMODEL];
__device__ bf16 g_wf1 [NLAYER * DMODEL * 4 * DMODEL];
__device__ bf16 g_wf2 [NLAYER * 4 * DMODEL * DMODEL];
__device__ bf16 g_wgen[DMODEL * NVOCAB];

// ---------------------------------------------------------------------------
// helpers
// ---------------------------------------------------------------------------
__device__ __forceinline__ unsigned pk2(float a, float b)
{
    bf162 t = __floats2bfloat162_rn(a, b);
    return *(unsigned*)&t;
}

__device__ __forceinline__ void mma_bf16(float* c, unsigned a0, unsigned a1,
                                         unsigned a2, unsigned a3,
                                         unsigned b0, unsigned b1)
{
    asm volatile(
        "mma.sync.aligned.m16n8k16.row.col.f32.bf16.bf16.f32 "
        "{%0,%1,%2,%3}, {%4,%5,%6,%7}, {%8,%9}, {%0,%1,%2,%3};"
        : "+f"(c[0]), "+f"(c[1]), "+f"(c[2]), "+f"(c[3])
        : "r"(a0), "r"(a1), "r"(a2), "r"(a3), "r"(b0), "r"(b1));
}

__device__ __forceinline__ void ldsm4(unsigned& r0, unsigned& r1,
                                      unsigned& r2, unsigned& r3, const void* p)
{
    unsigned a = (unsigned)__cvta_generic_to_shared(p);
    asm volatile("ldmatrix.sync.aligned.m8n8.x4.shared.b16 {%0,%1,%2,%3}, [%4];"
                 : "=r"(r0), "=r"(r1), "=r"(r2), "=r"(r3) : "r"(a));
}

__device__ __forceinline__ void ldsm4t(unsigned& r0, unsigned& r1,
                                       unsigned& r2, unsigned& r3, const void* p)
{
    unsigned a = (unsigned)__cvta_generic_to_shared(p);
    asm volatile("ldmatrix.sync.aligned.m8n8.x4.trans.shared.b16 {%0,%1,%2,%3}, [%4];"
                 : "=r"(r0), "=r"(r1), "=r"(r2), "=r"(r3) : "r"(a));
}

__device__ __forceinline__ void cpa16(void* smem_dst, const void* gsrc)
{
    unsigned s = (unsigned)__cvta_generic_to_shared(smem_dst);
    asm volatile("cp.async.cg.shared.global [%0], [%1], 16;\n" :: "r"(s), "l"(gsrc));
}
__device__ __forceinline__ void cpa_commit()
{
    asm volatile("cp.async.commit_group;\n" ::: "memory");
}
__device__ __forceinline__ void cpa_wait2()
{
    asm volatile("cp.async.wait_group 2;\n" ::: "memory");
}

// ---------------------------------------------------------------------------
// Fused fp32->bf16 conversion of all 5 weight tensors (one launch)
// ---------------------------------------------------------------------------
__global__ void cvt5_k(const float4* __restrict__ q,  const float4* __restrict__ o,
                       const float4* __restrict__ f1, const float4* __restrict__ f2,
                       const float4* __restrict__ gw,
                       uint2* __restrict__ qd,  uint2* __restrict__ od,
                       uint2* __restrict__ f1d, uint2* __restrict__ f2d,
                       uint2* __restrict__ gd)
{
    int i = blockIdx.x * 256 + threadIdx.x;
    const float4* s; uint2* d; int j = i;
    if (j < 98304)                    { s = q;  d = qd;  }
    else if ((j -= 98304)  < 32768)   { s = o;  d = od;  }
    else if ((j -= 32768)  < 131072)  { s = f1; d = f1d; }
    else if ((j -= 131072) < 131072)  { s = f2; d = f2d; }
    else { j -= 131072;                 s = gw; d = gd;  }
    float4 v = s[j];
    uint2 u;
    u.x = pk2(v.x, v.y);
    u.y = pk2(v.z, v.w);
    d[j] = u;
}

// ---------------------------------------------------------------------------
// Embedding
// ---------------------------------------------------------------------------
__global__ void embed_k(const int* __restrict__ tok, const int* __restrict__ pos,
                        const float* __restrict__ ve, const float* __restrict__ ce,
                        const float* __restrict__ pe, float* __restrict__ x)
{
    int n = blockIdx.x;
    int d = threadIdx.x;
    int p = pos[n];
    x[n * DMODEL + d] = ce[(p % 3) * DMODEL + d]
                      + pe[(p / 3) * DMODEL + d]
                      + ve[tok[n] * DMODEL + d];
}

// ---------------------------------------------------------------------------
// LayerNorm (standalone; only used for layer-0 ln1): warp per row.
// ---------------------------------------------------------------------------
__global__ void ln_k(const float* __restrict__ x, const float* __restrict__ s,
                     const float* __restrict__ b, bf16* __restrict__ y)
{
    int row  = blockIdx.x * 8 + (threadIdx.x >> 5);
    int lane = threadIdx.x & 31;
    const float4* xr = (const float4*)(x + (size_t)row * DMODEL);
    float4 v0 = xr[lane];
    float4 v1 = xr[lane + 32];

    float sum = v0.x + v0.y + v0.z + v0.w + v1.x + v1.y + v1.z + v1.w;
    #pragma unroll
    for (int o = 16; o > 0; o >>= 1) sum += __shfl_xor_sync(0xffffffffu, sum, o);
    float mu = sum * (1.0f / DMODEL);

    float d0x=v0.x-mu, d0y=v0.y-mu, d0z=v0.z-mu, d0w=v0.w-mu;
    float d1x=v1.x-mu, d1y=v1.y-mu, d1z=v1.z-mu, d1w=v1.w-mu;
    float sq = d0x*d0x+d0y*d0y+d0z*d0z+d0w*d0w + d1x*d1x+d1y*d1y+d1z*d1z+d1w*d1w;
    #pragma unroll
    for (int o = 16; o > 0; o >>= 1) sq += __shfl_xor_sync(0xffffffffu, sq, o);
    float rs = rsqrtf(sq * (1.0f / DMODEL) + 1e-5f);

    const float4* sv = (const float4*)s;
    const float4* bv = (const float4*)b;
    float4 s0 = sv[lane], s1 = sv[lane + 32];
    float4 b0 = bv[lane], b1 = bv[lane + 32];
    uint2 u0, u1;
    u0.x = pk2(d0x*rs*s0.x + b0.x, d0y*rs*s0.y + b0.y);
    u0.y = pk2(d0z*rs*s0.z + b0.z, d0w*rs*s0.w + b0.w);
    u1.x = pk2(d1x*rs*s1.x + b1.x, d1y*rs*s1.y + b1.y);
    u1.y = pk2(d1z*rs*s1.z + b1.z, d1w*rs*s1.w + b1.w);
    *(uint2*)(y + (size_t)row * DMODEL + lane * 4)        = u0;
    *(uint2*)(y + (size_t)row * DMODEL + (lane + 32) * 4) = u1;
}

// ---------------------------------------------------------------------------
// bf16 tensor-core attention (unchanged from R9)
// ---------------------------------------------------------------------------
__global__ __launch_bounds__(128)
void attn_k(const bf16* __restrict__ qkv, bf16* __restrict__ o)
{
    __shared__ bf16 sm[13824];
    __shared__ float zpart[4][96];
    __shared__ float zinv[96];

    int bh = blockIdx.x;
    int b = bh >> 3, h = bh & 7;
    int base = b * LSEQ;
    int tid  = threadIdx.x;
    int lane = tid & 31, wid = tid >> 5;
    int g = lane >> 2, lt = lane & 3;
    int ltile = lane >> 3, lr = lane & 7;
    int a_roff = (ltile & 1) * 8 + lr;
    int a_koff = (ltile >> 1) * 8;

    const bf16* Qg = qkv + (size_t)base * 768 + h * DKH;
    const bf16* Kg = Qg + DMODEL;
    const bf16* Vg = Qg + 2 * DMODEL;

    unsigned vreg[6][2];
    int d0 = 8 * wid;
    #pragma unroll
    for (int kc = 0; kc < 6; kc++) {
        int k0 = 16 * kc + 2 * lt;
        unsigned lo0 = *(const unsigned short*)(Vg + (size_t)k0       * 768 + d0 + g);
        unsigned hi0 = *(const unsigned short*)(Vg + (size_t)(k0 + 1) * 768 + d0 + g);
        unsigned lo1 = *(const unsigned short*)(Vg + (size_t)(k0 + 8) * 768 + d0 + g);
        unsigned hi1 = *(const unsigned short*)(Vg + (size_t)(k0 + 9) * 768 + d0 + g);
        vreg[kc][0] = lo0 | (hi0 << 16);
        vreg[kc][1] = lo1 | (hi1 << 16);
    }

    for (int idx = tid; idx < 96 * 4; idx += 128) {
        int r = idx >> 2, q = idx & 3;
        int kc = q >> 1, off8 = (q & 1) * 8;
        uint4 qv = *(const uint4*)(Qg + (size_t)r * 768 + q * 8);
        uint4 kv = *(const uint4*)(Kg + (size_t)r * 768 + q * 8);
        *(uint4*)&sm[kc * 2304 + r * 24 + off8] = qv;
        *(uint4*)&sm[4608 + kc * 2304 + r * 24 + off8] = kv;
    }
    __syncthreads();

    float acc[6][3][4];
    #pragma unroll
    for (int i = 0; i < 6; i++)
        #pragma unroll
        for (int j = 0; j < 3; j++)
            #pragma unroll
            for (int v = 0; v < 4; v++) acc[i][j][v] = 0.0f;

    int J0 = 3 * wid;
    #pragma unroll
    for (int kc = 0; kc < 2; kc++) {
        unsigned s0, s1, s2, s3, t0, t1, t2, t3;
        ldsm4(s0, s1, s2, s3,
              &sm[4608 + kc * 2304 + (24 * wid + a_roff) * 24 + a_koff]);
        ldsm4(t0, t1, t2, t3,
              &sm[4608 + kc * 2304 + (24 * wid + 16 + a_roff) * 24 + a_koff]);
        (void)t1; (void)t3;

        #pragma unroll
        for (int i = 0; i < 6; i++) {
            if (8 * J0 > 16 * i + 15) continue;
            unsigned a0, a1, a2, a3;
            ldsm4(a0, a1, a2, a3, &sm[kc * 2304 + (16 * i + a_roff) * 24 + a_koff]);
            if (8 * (J0 + 0) <= 16 * i + 15) mma_bf16(acc[i][0], a0, a1, a2, a3, s0, s2);
            if (8 * (J0 + 1) <= 16 * i + 15) mma_bf16(acc[i][1], a0, a1, a2, a3, s1, s3);
            if (8 * (J0 + 2) <= 16 * i + 15) mma_bf16(acc[i][2], a0, a1, a2, a3, t0, t2);
        }
    }
    __syncthreads();

    float zp[12];
    #pragma unroll
    for (int m = 0; m < 12; m++) zp[m] = 0.0f;
    const float invs = 0.17677669529663687f;

    #pragma unroll
    for (int i = 0; i < 6; i++) {
        int r0 = 16 * i + g, r1 = r0 + 8;
        #pragma unroll
        for (int jl = 0; jl < 3; jl++) {
            int J = J0 + jl;
            if (8 * J > 16 * i + 15) continue;
            int c = 8 * J + 2 * lt;
            float w0 = (c     <= r0) ? __expf(fminf(fmaxf(acc[i][jl][0] * invs, -5.0f), 5.0f)) : 0.0f;
            float w1 = (c + 1 <= r0) ? __expf(fminf(fmaxf(acc[i][jl][1] * invs, -5.0f), 5.0f)) : 0.0f;
            float w2 = (c     <= r1) ? __expf(fminf(fmaxf(acc[i][jl][2] * invs, -5.0f), 5.0f)) : 0.0f;
            float w3 = (c + 1 <= r1) ? __expf(fminf(fmaxf(acc[i][jl][3] * invs, -5.0f), 5.0f)) : 0.0f;
            zp[2 * i]     += w0 + w1;
            zp[2 * i + 1] += w2 + w3;
            int col = (J & 1) * 8 + 2 * lt;
            *(unsigned*)&sm[(J >> 1) * 2304 + r0 * 24 + col] = pk2(w0, w1);
            *(unsigned*)&sm[(J >> 1) * 2304 + r1 * 24 + col] = pk2(w2, w3);
        }
    }
    #pragma unroll
    for (int off = 1; off <= 2; off <<= 1)
        #pragma unroll
        for (int m = 0; m < 12; m++)
            zp[m] += __shfl_xor_sync(0xffffffffu, zp[m], off);
    if (lt == 0) {
        #pragma unroll
        for (int i = 0; i < 6; i++) {
            zpart[wid][16 * i + g]     = zp[2 * i];
            zpart[wid][16 * i + 8 + g] = zp[2 * i + 1];
        }
    }
    __syncthreads();
    if (tid < 96)
        zinv[tid] = 1.0f / (zpart[0][tid] + zpart[1][tid] + zpart[2][tid] + zpart[3][tid]);
    __syncthreads();

    float oacc[6][4];
    #pragma unroll
    for (int i = 0; i < 6; i++)
        #pragma unroll
        for (int v = 0; v < 4; v++) oacc[i][v] = 0.0f;

    #pragma unroll
    for (int i = 0; i < 6; i++) {
        #pragma unroll
        for (int kc = 0; kc < 6; kc++) {
            if (kc > i) break;
            unsigned a0, a1, a2, a3;
            ldsm4(a0, a1, a2, a3, &sm[kc * 2304 + (16 * i + a_roff) * 24 + a_koff]);
            mma_bf16(oacc[i], a0, a1, a2, a3, vreg[kc][0], vreg[kc][1]);
        }
    }

    #pragma unroll
    for (int i = 0; i < 6; i++) {
        int r0 = 16 * i + g, r1 = r0 + 8;
        float zi0 = zinv[r0], zi1 = zinv[r1];
        unsigned u0 = pk2(oacc[i][0] * zi0, oacc[i][1] * zi0);
        unsigned u1 = pk2(oacc[i][2] * zi1, oacc[i][3] * zi1);
        *(unsigned*)(o + (size_t)(base + r0) * DMODEL + h * DKH + d0 + 2 * lt) = u0;
        *(unsigned*)(o + (size_t)(base + r1) * DMODEL + h * DKH + d0 + 2 * lt) = u1;
    }
}

// ---------------------------------------------------------------------------
// bf16 GEMM, BM=128 x 128 tile (R9 proven): KT=16, 4-stage cp.async ring,
// 8 warps, warp tile 32x64. OP: 0 bias, 1 bias+relu. OUTM bit0 fp32, bit1 bf16.
// ---------------------------------------------------------------------------
template<int OP, int OUTM>
__global__ __launch_bounds__(256, 2)
void hg128_k(const bf16* __restrict__ A, const bf16* __restrict__ B,
             const float* __restrict__ bias,
             float* __restrict__ C, bf16* __restrict__ Cb,
             int M, int N, int K)
{
    __shared__ bf16 As[4][128][24];
    __shared__ bf16 Bs[4][16][136];

    int tid  = threadIdx.x;
    int lane = tid & 31, wid = tid >> 5;
    int g = lane >> 2, lt = lane & 3;
    int wm = (wid % 4) * 32;
    int wn = (wid / 4) * 64;
    int m0 = blockIdx.y * 128;
    int n0 = blockIdx.x * 128;

    int ar   = tid >> 1;
    int ah   = (tid & 1) * 8;
    int brow = tid >> 4;
    int bc8  = (tid & 15) * 8;

    int ltile = lane >> 3, lr = lane & 7;
    int a_roff = (ltile & 1) * 8 + lr;
    int a_koff = (ltile >> 1) * 8;
    int b_roff = (ltile & 1) * 8 + lr;
    int b_coff = (ltile >> 1) * 8;

    float acc[2][8][4];
    #pragma unroll
    for (int i = 0; i < 2; i++)
        #pragma unroll
        for (int j = 0; j < 8; j++)
            #pragma unroll
            for (int v = 0; v < 4; v++) acc[i][j][v] = 0.0f;

    int T = K >> 4;

    auto issue = [&](int buf, int kt) {
        int k0 = kt * 16;
        cpa16(&As[buf][ar][ah], A + (size_t)(m0 + ar) * K + k0 + ah);
        cpa16(&Bs[buf][brow][bc8], B + (size_t)(k0 + brow) * N + n0 + bc8);
    };

    issue(0, 0); cpa_commit();
    issue(1, 1); cpa_commit();
    issue(2, 2); cpa_commit();

    for (int kt = 0; kt < T; kt++) {
        cpa_wait2();
        __syncthreads();
        if (kt + 3 < T) issue((kt + 3) & 3, kt + 3);
        cpa_commit();

        int buf = kt & 3;
        unsigned af[2][4], bf[8][2];
        #pragma unroll
        for (int i = 0; i < 2; i++)
            ldsm4(af[i][0], af[i][1], af[i][2], af[i][3],
                  &As[buf][wm + 16 * i + a_roff][a_koff]);
        #pragma unroll
        for (int jp = 0; jp < 4; jp++) {
            unsigned r0, r1, r2, r3;
            ldsm4t(r0, r1, r2, r3, &Bs[buf][b_roff][wn + 16 * jp + b_coff]);
            bf[2 * jp][0] = r0;  bf[2 * jp][1] = r1;
            bf[2 * jp + 1][0] = r2;  bf[2 * jp + 1][1] = r3;
        }
        #pragma unroll
        for (int i = 0; i < 2; i++)
            #pragma unroll
            for (int j = 0; j < 8; j++)
                mma_bf16(acc[i][j], af[i][0], af[i][1], af[i][2], af[i][3],
                         bf[j][0], bf[j][1]);
    }

    // epilogue
    #pragma unroll
    for (int i = 0; i < 2; i++) {
        int r0 = m0 + wm + 16 * i + g;
        #pragma unroll
        for (int j = 0; j < 8; j++) {
            int c = n0 + wn + 8 * j + 2 * lt;
            float bx = bias[c], by = bias[c + 1];
            float2 v0, v1;
            v0.x = acc[i][j][0] + bx;  v0.y = acc[i][j][1] + by;
            v1.x = acc[i][j][2] + bx;  v1.y = acc[i][j][3] + by;
            if (OP == 1) {
                v0.x = fmaxf(v0.x, 0.0f); v0.y = fmaxf(v0.y, 0.0f);
                v1.x = fmaxf(v1.x, 0.0f); v1.y = fmaxf(v1.y, 0.0f);
            }
            if (OUTM & 1) {
                *(float2*)(C + (size_t)r0 * N + c) = v0;
                *(float2*)(C + (size_t)(r0 + 8) * N + c) = v1;
            }
            if (OUTM & 2) {
                *(unsigned*)(Cb + (size_t)r0 * N + c) = pk2(v0.x, v0.y);
                *(unsigned*)(Cb + (size_t)(r0 + 8) * N + c) = pk2(v1.x, v1.y);
            }
        }
    }
}

// ---------------------------------------------------------------------------
// Fused GEMM(+bias+residual)+LayerNorm kernel for N=256 GEMMs (wo, ff2).
// Block tile 64x256 covers FULL rows -> LN computed in epilogue.
// DO_LN=1: writes x (fp32) and xn = LN(x) (bf16).
// DO_LN=0: writes x (fp32) and xb = bf16(x).
// Mainloop identical to R9's proven 4-stage pipeline; B stride 264 keeps
// ldsm4t conflict-free (row*132+col granule banks distinct mod 32).
// ---------------------------------------------------------------------------
template<int DO_LN>
__global__ __launch_bounds__(256)
void g64ln_k(const bf16* __restrict__ A, const bf16* __restrict__ B,
             const float* __restrict__ bias, const float* __restrict__ res,
             float* __restrict__ C, bf16* __restrict__ Cb,
             const float* __restrict__ lns, const float* __restrict__ lnb,
             int K)
{
    constexpr int N = 256;
    __shared__ bf16 As[4][64][24];
    __shared__ bf16 Bs[4][16][264];
    __shared__ float redS[64][4];
    __shared__ float redQ[64][4];

    int tid  = threadIdx.x;
    int lane = tid & 31, wid = tid >> 5;
    int g = lane >> 2, lt = lane & 3;
    int wm = (wid & 1) * 32;         // 2 warps along M
    int wn = (wid >> 1) * 64;        // 4 warps along N
    int m0 = blockIdx.x * 64;

    int ltile = lane >> 3, lr = lane & 7;
    int a_roff = (ltile & 1) * 8 + lr;
    int a_koff = (ltile >> 1) * 8;
    int b_roff = (ltile & 1) * 8 + lr;
    int b_coff = (ltile >> 1) * 8;

    float acc[2][8][4];
    #pragma unroll
    for (int i = 0; i < 2; i++)
        #pragma unroll
        for (int j = 0; j < 8; j++)
            #pragma unroll
            for (int v = 0; v < 4; v++) acc[i][j][v] = 0.0f;

    int T = K >> 4;

    auto issue = [&](int buf, int kt) {
        int k0 = kt * 16;
        if (tid < 128)
            cpa16(&As[buf][tid >> 1][(tid & 1) * 8],
                  A + (size_t)(m0 + (tid >> 1)) * K + k0 + (tid & 1) * 8);
        #pragma unroll
        for (int jj = 0; jj < 2; jj++) {
            int idx = tid + jj * 256;
            int br = idx >> 5, bc = (idx & 31) * 8;
            cpa16(&Bs[buf][br][bc], B + (size_t)(k0 + br) * N + bc);
        }
    };

    issue(0, 0); cpa_commit();
    issue(1, 1); cpa_commit();
    issue(2, 2); cpa_commit();

    for (int kt = 0; kt < T; kt++) {
        cpa_wait2();
        __syncthreads();
        if (kt + 3 < T) issue((kt + 3) & 3, kt + 3);
        cpa_commit();

        int buf = kt & 3;
        unsigned af[2][4], bf[8][2];
        #pragma unroll
        for (int i = 0; i < 2; i++)
            ldsm4(af[i][0], af[i][1], af[i][2], af[i][3],
                  &As[buf][wm + 16 * i + a_roff][a_koff]);
        #pragma unroll
        for (int jp = 0; jp < 4; jp++) {
            unsigned r0, r1, r2, r3;
            ldsm4t(r0, r1, r2, r3, &Bs[buf][b_roff][wn + 16 * jp + b_coff]);
            bf[2 * jp][0] = r0;  bf[2 * jp][1] = r1;
            bf[2 * jp + 1][0] = r2;  bf[2 * jp + 1][1] = r3;
        }
        #pragma unroll
        for (int i = 0; i < 2; i++)
            #pragma unroll
            for (int j = 0; j < 8; j++)
                mma_bf16(acc[i][j], af[i][0], af[i][1], af[i][2], af[i][3],
                         bf[j][0], bf[j][1]);
    }

    // ---- epilogue: bias + residual -> x; then LN (or bf16 copy) ----
    // rows per thread: rr = 2i+h -> local row wm + 16i + 8h + g
    float vals[4][16];
    #pragma unroll
    for (int i = 0; i < 2; i++) {
        int rA = m0 + wm + 16 * i + g;
        #pragma unroll
        for (int j = 0; j < 8; j++) {
            int c = wn + 8 * j + 2 * lt;
            float bx = bias[c], by = bias[c + 1];
            float2 rv0 = *(const float2*)(res + (size_t)rA * N + c);
            float2 rv1 = *(const float2*)(res + (size_t)(rA + 8) * N + c);
            float v0x = acc[i][j][0] + bx + rv0.x;
            float v0y = acc[i][j][1] + by + rv0.y;
            float v1x = acc[i][j][2] + bx + rv1.x;
            float v1y = acc[i][j][3] + by + rv1.y;
            vals[2 * i][2 * j]     = v0x;  vals[2 * i][2 * j + 1]     = v0y;
            vals[2 * i + 1][2 * j] = v1x;  vals[2 * i + 1][2 * j + 1] = v1y;
            float2 w0; w0.x = v0x; w0.y = v0y;
            float2 w1; w1.x = v1x; w1.y = v1y;
            *(float2*)(C + (size_t)rA * N + c) = w0;
            *(float2*)(C + (size_t)(rA + 8) * N + c) = w1;
        }
    }

    if (DO_LN) {
        // per-row sum & sumsq partials (this warp covers 64 of 256 cols)
        #pragma unroll
        for (int rr = 0; rr < 4; rr++) {
            float s = 0.0f, q = 0.0f;
            #pragma unroll
            for (int t = 0; t < 16; t++) { s += vals[rr][t]; q += vals[rr][t] * vals[rr][t]; }
            #pragma unroll
            for (int off = 1; off <= 2; off <<= 1) {
                s += __shfl_xor_sync(0xffffffffu, s, off);
                q += __shfl_xor_sync(0xffffffffu, q, off);
            }
            if (lt == 0) {
                int lrow = wm + 16 * (rr >> 1) + 8 * (rr & 1) + g;
                redS[lrow][wid >> 1] = s;
                redQ[lrow][wid >> 1] = q;
            }
        }
        __syncthreads();
        #pragma unroll
        for (int rr = 0; rr < 4; rr++) {
            int lrow = wm + 16 * (rr >> 1) + 8 * (rr & 1) + g;
            float S = redS[lrow][0] + redS[lrow][1] + redS[lrow][2] + redS[lrow][3];
            float Q = redQ[lrow][0] + redQ[lrow][1] + redQ[lrow][2] + redQ[lrow][3];
            float mu = S * (1.0f / 256.0f);
            float var = Q * (1.0f / 256.0f) - mu * mu;
            float rs = rsqrtf(var + 1e-5f);
            int row = m0 + lrow;
            #pragma unroll
            for (int j = 0; j < 8; j++) {
                int c = wn + 8 * j + 2 * lt;
                float x0 = (vals[rr][2 * j]     - mu) * rs * lns[c]     + lnb[c];
                float x1 = (vals[rr][2 * j + 1] - mu) * rs * lns[c + 1] + lnb[c + 1];
                *(unsigned*)(Cb + (size_t)row * N + c) = pk2(x0, x1);
            }
        }
    } else {
        #pragma unroll
        for (int rr = 0; rr < 4; rr++) {
            int row = m0 + wm + 16 * (rr >> 1) + 8 * (rr & 1) + g;
            #pragma unroll
            for (int j = 0; j < 8; j++) {
                int c = wn + 8 * j + 2 * lt;
                *(unsigned*)(Cb + (size_t)row * N + c)
                    = pk2(vals[rr][2 * j], vals[rr][2 * j + 1]);
            }
        }
    }
}

// ---------------------------------------------------------------------------
// In-place log_softmax over VOCAB=1024
// ---------------------------------------------------------------------------
__global__ void lsm_k(float* __restrict__ out)
{
    __shared__ float red[256];
    int n = blockIdx.x, t = threadIdx.x;
    float v[4];
    #pragma unroll
    for (int j = 0; j < 4; j++) v[j] = out[(size_t)n * NVOCAB + t + j * 256];

    float m = fmaxf(fmaxf(v[0], v[1]), fmaxf(v[2], v[3]));
    red[t] = m;
    __syncthreads();
    #pragma unroll
    for (int o = 128; o > 0; o >>= 1) {
        if (t < o) red[t] = fmaxf(red[t], red[t + o]);
        __syncthreads();
    }
    float M = red[0];
    __syncthreads();

    float s = 0.0f;
    #pragma unroll
    for (int j = 0; j < 4; j++) s += __expf(v[j] - M);
    red[t] = s;
    __syncthreads();
    #pragma unroll
    for (int o = 128; o > 0; o >>= 1) {
        if (t < o) red[t] += red[t + o];
        __syncthreads();
    }
    float lse = M + __logf(red[0]);

    #pragma unroll
    for (int j = 0; j < 4; j++)
        out[(size_t)n * NVOCAB + t + j * 256] = v[j] - lse;
}

// ---------------------------------------------------------------------------
// Launch
// ---------------------------------------------------------------------------
extern "C" void kernel_launch(void* const* d_in, const int* in_sizes, int n_in,
                              void* d_out, int out_size)
{
    const int*   tokens    = (const int*)  d_in[0];
    const int*   pos_idx   = (const int*)  d_in[1];
    const float* value_emb = (const float*)d_in[4];
    const float* coord_emb = (const float*)d_in[5];
    const float* pos_emb   = (const float*)d_in[6];
    const float* ln1_s     = (const float*)d_in[7];
    const float* ln1_b     = (const float*)d_in[8];
    const float* W_qkv     = (const float*)d_in[9];
    const float* b_qkv     = (const float*)d_in[10];
    const float* W_o       = (const float*)d_in[11];
    const float* b_o       = (const float*)d_in[12];
    const float* ln2_s     = (const float*)d_in[13];
    const float* ln2_b     = (const float*)d_in[14];
    const float* W_ff1     = (const float*)d_in[15];
    const float* b_ff1     = (const float*)d_in[16];
    const float* W_ff2     = (const float*)d_in[17];
    const float* b_ff2     = (const float*)d_in[18];
    const float* W_gen     = (const float*)d_in[19];
    const float* b_gen     = (const float*)d_in[20];
    float* out = (float*)d_out;

    float *x;
    bf16 *qkvb, *xn, *att, *mid, *xb;
    bf16 *wqkvb, *wob, *wf1b, *wf2b, *wgenb;
    cudaGetSymbolAddress((void**)&x,    g_x);
    cudaGetSymbolAddress((void**)&qkvb, g_qkvb);
    cudaGetSymbolAddress((void**)&xn,   g_xn);
    cudaGetSymbolAddress((void**)&att,  g_att);
    cudaGetSymbolAddress((void**)&mid,  g_mid);
    cudaGetSymbolAddress((void**)&xb,   g_xb);
    cudaGetSymbolAddress((void**)&wqkvb, g_wqkv);
    cudaGetSymbolAddress((void**)&wob,   g_wo);
    cudaGetSymbolAddress((void**)&wf1b,  g_wf1);
    cudaGetSymbolAddress((void**)&wf2b,  g_wf2);
    cudaGetSymbolAddress((void**)&wgenb, g_wgen);

    cvt5_k<<<1792, 256>>>((const float4*)W_qkv, (const float4*)W_o,
                          (const float4*)W_ff1, (const float4*)W_ff2,
                          (const float4*)W_gen,
                          (uint2*)wqkvb, (uint2*)wob, (uint2*)wf1b,
                          (uint2*)wf2b, (uint2*)wgenb);

    embed_k<<<NTOK, DMODEL>>>(tokens, pos_idx, value_emb, coord_emb, pos_emb, x);

    // layer-0 ln1 (subsequent ln1/ln2 are fused into GEMM epilogues)
    ln_k<<<NTOK / 8, 256>>>(x, ln1_s, ln1_b, xn);

    for (int l = 0; l < NLAYER; l++) {
        const bf16* wqkv = wqkvb + (size_t)l * DMODEL * 3 * DMODEL;
        const float* bqkv = b_qkv + (size_t)l * 3 * DMODEL;
        const bf16* wo    = wob   + (size_t)l * DMODEL * DMODEL;
        const float* bo   = b_o   + (size_t)l * DMODEL;
        const bf16* wf1   = wf1b  + (size_t)l * DMODEL * 4 * DMODEL;
        const float* bf1  = b_ff1 + (size_t)l * 4 * DMODEL;
        const bf16* wf2   = wf2b  + (size_t)l * 4 * DMODEL * DMODEL;
        const float* bf2  = b_ff2 + (size_t)l * DMODEL;

        { dim3 g(3 * DMODEL / 128, NTOK / 128);
          hg128_k<0, 2><<<g, 256>>>(xn, wqkv, bqkv, nullptr, qkvb,
                                    NTOK, 3 * DMODEL, DMODEL); }

        attn_k<<<NBATCH * NHEAD, 128>>>(qkvb, att);

        // wo GEMM + residual + ln2 fused
        g64ln_k<1><<<NTOK / 64, 256>>>(att, wo, bo, x, x, xn,
                                       ln2_s + l * DMODEL, ln2_b + l * DMODEL, 256);

        { dim3 g(4 * DMODEL / 128, NTOK / 128);
          hg128_k<1, 2><<<g, 256>>>(xn, wf1, bf1, nullptr, mid,
                                    NTOK, 4 * DMODEL, DMODEL); }

        // ff2 GEMM + residual, fused with next layer's ln1 (or xb for generator)
        if (l + 1 < NLAYER) {
            g64ln_k<1><<<NTOK / 64, 256>>>(mid, wf2, bf2, x, x, xn,
                                           ln1_s + (l + 1) * DMODEL,
                                           ln1_b + (l + 1) * DMODEL, 1024);
        } else {
            g64ln_k<0><<<NTOK / 64, 256>>>(mid, wf2, bf2, x, x, xb,
                                           nullptr, nullptr, 1024);
        }
    }

    { dim3 g(NVOCAB / 128, NTOK / 128);
      hg128_k<0, 1><<<g, 256>>>(xb, wgenb, b_gen, out, nullptr,
                                NTOK, NVOCAB, DMODEL); }

    lsm_k<<<NTOK, 256>>>(out);
}

// round 17
// speedup vs baseline: 1.1777x; 1.0198x over previous
#include <cuda_runtime.h>
#include <cuda_bf16.h>
#include <cstdint>
#include <math.h>

#define NTOK 6144
#define DMODEL 256
#define NHEAD 8
#define DKH 32
#define NLAYER 2
#define NVOCAB 1024
#define LSEQ 96
#define NBATCH 64

typedef __nv_bfloat16 bf16;
typedef __nv_bfloat162 bf162;

// ---------------------------------------------------------------------------
// Scratch
// ---------------------------------------------------------------------------
__device__ float g_x  [NTOK * DMODEL];
__device__ bf16  g_qkvb[NTOK * 3 * DMODEL];
__device__ bf16  g_xn [NTOK * DMODEL];
__device__ bf16  g_att[NTOK * DMODEL];
__device__ bf16  g_mid[NTOK * 4 * DMODEL];
__device__ bf16  g_xb [NTOK * DMODEL];
__device__ bf16 g_wqkv[NLAYER * DMODEL * 3 * DMODEL];
__device__ bf16 g_wo  [NLAYER * DMODEL * DMODEL];
__device__ bf16 g_wf1 [NLAYER * DMODEL * 4 * DMODEL];
__device__ bf16 g_wf2 [NLAYER * 4 * DMODEL * DMODEL];
__device__ bf16 g_wgen[DMODEL * NVOCAB];

// ---------------------------------------------------------------------------
// helpers
// ---------------------------------------------------------------------------
__device__ __forceinline__ unsigned pk2(float a, float b)
{
    bf162 t = __floats2bfloat162_rn(a, b);
    return *(unsigned*)&t;
}

__device__ __forceinline__ void mma_bf16(float* c, unsigned a0, unsigned a1,
                                         unsigned a2, unsigned a3,
                                         unsigned b0, unsigned b1)
{
    asm volatile(
        "mma.sync.aligned.m16n8k16.row.col.f32.bf16.bf16.f32 "
        "{%0,%1,%2,%3}, {%4,%5,%6,%7}, {%8,%9}, {%0,%1,%2,%3};"
        : "+f"(c[0]), "+f"(c[1]), "+f"(c[2]), "+f"(c[3])
        : "r"(a0), "r"(a1), "r"(a2), "r"(a3), "r"(b0), "r"(b1));
}

__device__ __forceinline__ void ldsm4(unsigned& r0, unsigned& r1,
                                      unsigned& r2, unsigned& r3, const void* p)
{
    unsigned a = (unsigned)__cvta_generic_to_shared(p);
    asm volatile("ldmatrix.sync.aligned.m8n8.x4.shared.b16 {%0,%1,%2,%3}, [%4];"
                 : "=r"(r0), "=r"(r1), "=r"(r2), "=r"(r3) : "r"(a));
}

__device__ __forceinline__ void ldsm4t(unsigned& r0, unsigned& r1,
                                       unsigned& r2, unsigned& r3, const void* p)
{
    unsigned a = (unsigned)__cvta_generic_to_shared(p);
    asm volatile("ldmatrix.sync.aligned.m8n8.x4.trans.shared.b16 {%0,%1,%2,%3}, [%4];"
                 : "=r"(r0), "=r"(r1), "=r"(r2), "=r"(r3) : "r"(a));
}

__device__ __forceinline__ void cpa16(void* smem_dst, const void* gsrc)
{
    unsigned s = (unsigned)__cvta_generic_to_shared(smem_dst);
    asm volatile("cp.async.cg.shared.global [%0], [%1], 16;\n" :: "r"(s), "l"(gsrc));
}
__device__ __forceinline__ void cpa_commit()
{
    asm volatile("cp.async.commit_group;\n" ::: "memory");
}
__device__ __forceinline__ void cpa_wait2()
{
    asm volatile("cp.async.wait_group 2;\n" ::: "memory");
}

// ---------------------------------------------------------------------------
// Fused fp32->bf16 conversion of all 5 weight tensors (one launch)
// ---------------------------------------------------------------------------
__global__ void cvt5_k(const float4* __restrict__ q,  const float4* __restrict__ o,
                       const float4* __restrict__ f1, const float4* __restrict__ f2,
                       const float4* __restrict__ gw,
                       uint2* __restrict__ qd,  uint2* __restrict__ od,
                       uint2* __restrict__ f1d, uint2* __restrict__ f2d,
                       uint2* __restrict__ gd)
{
    int i = blockIdx.x * 256 + threadIdx.x;
    const float4* s; uint2* d; int j = i;
    if (j < 98304)                    { s = q;  d = qd;  }
    else if ((j -= 98304)  < 32768)   { s = o;  d = od;  }
    else if ((j -= 32768)  < 131072)  { s = f1; d = f1d; }
    else if ((j -= 131072) < 131072)  { s = f2; d = f2d; }
    else { j -= 131072;                 s = gw; d = gd;  }
    float4 v = s[j];
    uint2 u;
    u.x = pk2(v.x, v.y);
    u.y = pk2(v.z, v.w);
    d[j] = u;
}

// ---------------------------------------------------------------------------
// Embedding
// ---------------------------------------------------------------------------
__global__ void embed_k(const int* __restrict__ tok, const int* __restrict__ pos,
                        const float* __restrict__ ve, const float* __restrict__ ce,
                        const float* __restrict__ pe, float* __restrict__ x)
{
    int n = blockIdx.x;
    int d = threadIdx.x;
    int p = pos[n];
    x[n * DMODEL + d] = ce[(p % 3) * DMODEL + d]
                      + pe[(p / 3) * DMODEL + d]
                      + ve[tok[n] * DMODEL + d];
}

// ---------------------------------------------------------------------------
// LayerNorm (standalone; only used for layer-0 ln1): warp per row.
// ---------------------------------------------------------------------------
__global__ void ln_k(const float* __restrict__ x, const float* __restrict__ s,
                     const float* __restrict__ b, bf16* __restrict__ y)
{
    int row  = blockIdx.x * 8 + (threadIdx.x >> 5);
    int lane = threadIdx.x & 31;
    const float4* xr = (const float4*)(x + (size_t)row * DMODEL);
    float4 v0 = xr[lane];
    float4 v1 = xr[lane + 32];

    float sum = v0.x + v0.y + v0.z + v0.w + v1.x + v1.y + v1.z + v1.w;
    #pragma unroll
    for (int o = 16; o > 0; o >>= 1) sum += __shfl_xor_sync(0xffffffffu, sum, o);
    float mu = sum * (1.0f / DMODEL);

    float d0x=v0.x-mu, d0y=v0.y-mu, d0z=v0.z-mu, d0w=v0.w-mu;
    float d1x=v1.x-mu, d1y=v1.y-mu, d1z=v1.z-mu, d1w=v1.w-mu;
    float sq = d0x*d0x+d0y*d0y+d0z*d0z+d0w*d0w + d1x*d1x+d1y*d1y+d1z*d1z+d1w*d1w;
    #pragma unroll
    for (int o = 16; o > 0; o >>= 1) sq += __shfl_xor_sync(0xffffffffu, sq, o);
    float rs = rsqrtf(sq * (1.0f / DMODEL) + 1e-5f);

    const float4* sv = (const float4*)s;
    const float4* bv = (const float4*)b;
    float4 s0 = sv[lane], s1 = sv[lane + 32];
    float4 b0 = bv[lane], b1 = bv[lane + 32];
    uint2 u0, u1;
    u0.x = pk2(d0x*rs*s0.x + b0.x, d0y*rs*s0.y + b0.y);
    u0.y = pk2(d0z*rs*s0.z + b0.z, d0w*rs*s0.w + b0.w);
    u1.x = pk2(d1x*rs*s1.x + b1.x, d1y*rs*s1.y + b1.y);
    u1.y = pk2(d1z*rs*s1.z + b1.z, d1w*rs*s1.w + b1.w);
    *(uint2*)(y + (size_t)row * DMODEL + lane * 4)        = u0;
    *(uint2*)(y + (size_t)row * DMODEL + (lane + 32) * 4) = u1;
}

// ---------------------------------------------------------------------------
// bf16 tensor-core attention (unchanged from R9)
// ---------------------------------------------------------------------------
__global__ __launch_bounds__(128)
void attn_k(const bf16* __restrict__ qkv, bf16* __restrict__ o)
{
    __shared__ bf16 sm[13824];
    __shared__ float zpart[4][96];
    __shared__ float zinv[96];

    int bh = blockIdx.x;
    int b = bh >> 3, h = bh & 7;
    int base = b * LSEQ;
    int tid  = threadIdx.x;
    int lane = tid & 31, wid = tid >> 5;
    int g = lane >> 2, lt = lane & 3;
    int ltile = lane >> 3, lr = lane & 7;
    int a_roff = (ltile & 1) * 8 + lr;
    int a_koff = (ltile >> 1) * 8;

    const bf16* Qg = qkv + (size_t)base * 768 + h * DKH;
    const bf16* Kg = Qg + DMODEL;
    const bf16* Vg = Qg + 2 * DMODEL;

    unsigned vreg[6][2];
    int d0 = 8 * wid;
    #pragma unroll
    for (int kc = 0; kc < 6; kc++) {
        int k0 = 16 * kc + 2 * lt;
        unsigned lo0 = *(const unsigned short*)(Vg + (size_t)k0       * 768 + d0 + g);
        unsigned hi0 = *(const unsigned short*)(Vg + (size_t)(k0 + 1) * 768 + d0 + g);
        unsigned lo1 = *(const unsigned short*)(Vg + (size_t)(k0 + 8) * 768 + d0 + g);
        unsigned hi1 = *(const unsigned short*)(Vg + (size_t)(k0 + 9) * 768 + d0 + g);
        vreg[kc][0] = lo0 | (hi0 << 16);
        vreg[kc][1] = lo1 | (hi1 << 16);
    }

    for (int idx = tid; idx < 96 * 4; idx += 128) {
        int r = idx >> 2, q = idx & 3;
        int kc = q >> 1, off8 = (q & 1) * 8;
        uint4 qv = *(const uint4*)(Qg + (size_t)r * 768 + q * 8);
        uint4 kv = *(const uint4*)(Kg + (size_t)r * 768 + q * 8);
        *(uint4*)&sm[kc * 2304 + r * 24 + off8] = qv;
        *(uint4*)&sm[4608 + kc * 2304 + r * 24 + off8] = kv;
    }
    __syncthreads();

    float acc[6][3][4];
    #pragma unroll
    for (int i = 0; i < 6; i++)
        #pragma unroll
        for (int j = 0; j < 3; j++)
            #pragma unroll
            for (int v = 0; v < 4; v++) acc[i][j][v] = 0.0f;

    int J0 = 3 * wid;
    #pragma unroll
    for (int kc = 0; kc < 2; kc++) {
        unsigned s0, s1, s2, s3, t0, t1, t2, t3;
        ldsm4(s0, s1, s2, s3,
              &sm[4608 + kc * 2304 + (24 * wid + a_roff) * 24 + a_koff]);
        ldsm4(t0, t1, t2, t3,
              &sm[4608 + kc * 2304 + (24 * wid + 16 + a_roff) * 24 + a_koff]);
        (void)t1; (void)t3;

        #pragma unroll
        for (int i = 0; i < 6; i++) {
            if (8 * J0 > 16 * i + 15) continue;
            unsigned a0, a1, a2, a3;
            ldsm4(a0, a1, a2, a3, &sm[kc * 2304 + (16 * i + a_roff) * 24 + a_koff]);
            if (8 * (J0 + 0) <= 16 * i + 15) mma_bf16(acc[i][0], a0, a1, a2, a3, s0, s2);
            if (8 * (J0 + 1) <= 16 * i + 15) mma_bf16(acc[i][1], a0, a1, a2, a3, s1, s3);
            if (8 * (J0 + 2) <= 16 * i + 15) mma_bf16(acc[i][2], a0, a1, a2, a3, t0, t2);
        }
    }
    __syncthreads();

    float zp[12];
    #pragma unroll
    for (int m = 0; m < 12; m++) zp[m] = 0.0f;
    const float invs = 0.17677669529663687f;

    #pragma unroll
    for (int i = 0; i < 6; i++) {
        int r0 = 16 * i + g, r1 = r0 + 8;
        #pragma unroll
        for (int jl = 0; jl < 3; jl++) {
            int J = J0 + jl;
            if (8 * J > 16 * i + 15) continue;
            int c = 8 * J + 2 * lt;
            float w0 = (c     <= r0) ? __expf(fminf(fmaxf(acc[i][jl][0] * invs, -5.0f), 5.0f)) : 0.0f;
            float w1 = (c + 1 <= r0) ? __expf(fminf(fmaxf(acc[i][jl][1] * invs, -5.0f), 5.0f)) : 0.0f;
            float w2 = (c     <= r1) ? __expf(fminf(fmaxf(acc[i][jl][2] * invs, -5.0f), 5.0f)) : 0.0f;
            float w3 = (c + 1 <= r1) ? __expf(fminf(fmaxf(acc[i][jl][3] * invs, -5.0f), 5.0f)) : 0.0f;
            zp[2 * i]     += w0 + w1;
            zp[2 * i + 1] += w2 + w3;
            int col = (J & 1) * 8 + 2 * lt;
            *(unsigned*)&sm[(J >> 1) * 2304 + r0 * 24 + col] = pk2(w0, w1);
            *(unsigned*)&sm[(J >> 1) * 2304 + r1 * 24 + col] = pk2(w2, w3);
        }
    }
    #pragma unroll
    for (int off = 1; off <= 2; off <<= 1)
        #pragma unroll
        for (int m = 0; m < 12; m++)
            zp[m] += __shfl_xor_sync(0xffffffffu, zp[m], off);
    if (lt == 0) {
        #pragma unroll
        for (int i = 0; i < 6; i++) {
            zpart[wid][16 * i + g]     = zp[2 * i];
            zpart[wid][16 * i + 8 + g] = zp[2 * i + 1];
        }
    }
    __syncthreads();
    if (tid < 96)
        zinv[tid] = 1.0f / (zpart[0][tid] + zpart[1][tid] + zpart[2][tid] + zpart[3][tid]);
    __syncthreads();

    float oacc[6][4];
    #pragma unroll
    for (int i = 0; i < 6; i++)
        #pragma unroll
        for (int v = 0; v < 4; v++) oacc[i][v] = 0.0f;

    #pragma unroll
    for (int i = 0; i < 6; i++) {
        #pragma unroll
        for (int kc = 0; kc < 6; kc++) {
            if (kc > i) break;
            unsigned a0, a1, a2, a3;
            ldsm4(a0, a1, a2, a3, &sm[kc * 2304 + (16 * i + a_roff) * 24 + a_koff]);
            mma_bf16(oacc[i], a0, a1, a2, a3, vreg[kc][0], vreg[kc][1]);
        }
    }

    #pragma unroll
    for (int i = 0; i < 6; i++) {
        int r0 = 16 * i + g, r1 = r0 + 8;
        float zi0 = zinv[r0], zi1 = zinv[r1];
        unsigned u0 = pk2(oacc[i][0] * zi0, oacc[i][1] * zi0);
        unsigned u1 = pk2(oacc[i][2] * zi1, oacc[i][3] * zi1);
        *(unsigned*)(o + (size_t)(base + r0) * DMODEL + h * DKH + d0 + 2 * lt) = u0;
        *(unsigned*)(o + (size_t)(base + r1) * DMODEL + h * DKH + d0 + 2 * lt) = u1;
    }
}

// ---------------------------------------------------------------------------
// bf16 GEMM, BM=128 x 128 tile (R9 proven): KT=16, 4-stage cp.async ring,
// 8 warps, warp tile 32x64. OP: 0 bias, 1 bias+relu. OUTM bit0 fp32, bit1 bf16.
// ---------------------------------------------------------------------------
template<int OP, int OUTM>
__global__ __launch_bounds__(256, 2)
void hg128_k(const bf16* __restrict__ A, const bf16* __restrict__ B,
             const float* __restrict__ bias,
             float* __restrict__ C, bf16* __restrict__ Cb,
             int M, int N, int K)
{
    __shared__ bf16 As[4][128][24];
    __shared__ bf16 Bs[4][16][136];

    int tid  = threadIdx.x;
    int lane = tid & 31, wid = tid >> 5;
    int g = lane >> 2, lt = lane & 3;
    int wm = (wid % 4) * 32;
    int wn = (wid / 4) * 64;
    int m0 = blockIdx.y * 128;
    int n0 = blockIdx.x * 128;

    int ar   = tid >> 1;
    int ah   = (tid & 1) * 8;
    int brow = tid >> 4;
    int bc8  = (tid & 15) * 8;

    int ltile = lane >> 3, lr = lane & 7;
    int a_roff = (ltile & 1) * 8 + lr;
    int a_koff = (ltile >> 1) * 8;
    int b_roff = (ltile & 1) * 8 + lr;
    int b_coff = (ltile >> 1) * 8;

    float acc[2][8][4];
    #pragma unroll
    for (int i = 0; i < 2; i++)
        #pragma unroll
        for (int j = 0; j < 8; j++)
            #pragma unroll
            for (int v = 0; v < 4; v++) acc[i][j][v] = 0.0f;

    int T = K >> 4;

    auto issue = [&](int buf, int kt) {
        int k0 = kt * 16;
        cpa16(&As[buf][ar][ah], A + (size_t)(m0 + ar) * K + k0 + ah);
        cpa16(&Bs[buf][brow][bc8], B + (size_t)(k0 + brow) * N + n0 + bc8);
    };

    issue(0, 0); cpa_commit();
    issue(1, 1); cpa_commit();
    issue(2, 2); cpa_commit();

    for (int kt = 0; kt < T; kt++) {
        cpa_wait2();
        __syncthreads();
        if (kt + 3 < T) issue((kt + 3) & 3, kt + 3);
        cpa_commit();

        int buf = kt & 3;
        unsigned af[2][4], bf[8][2];
        #pragma unroll
        for (int i = 0; i < 2; i++)
            ldsm4(af[i][0], af[i][1], af[i][2], af[i][3],
                  &As[buf][wm + 16 * i + a_roff][a_koff]);
        #pragma unroll
        for (int jp = 0; jp < 4; jp++) {
            unsigned r0, r1, r2, r3;
            ldsm4t(r0, r1, r2, r3, &Bs[buf][b_roff][wn + 16 * jp + b_coff]);
            bf[2 * jp][0] = r0;  bf[2 * jp][1] = r1;
            bf[2 * jp + 1][0] = r2;  bf[2 * jp + 1][1] = r3;
        }
        #pragma unroll
        for (int i = 0; i < 2; i++)
            #pragma unroll
            for (int j = 0; j < 8; j++)
                mma_bf16(acc[i][j], af[i][0], af[i][1], af[i][2], af[i][3],
                         bf[j][0], bf[j][1]);
    }

    // epilogue
    #pragma unroll
    for (int i = 0; i < 2; i++) {
        int r0 = m0 + wm + 16 * i + g;
        #pragma unroll
        for (int j = 0; j < 8; j++) {
            int c = n0 + wn + 8 * j + 2 * lt;
            float bx = bias[c], by = bias[c + 1];
            float2 v0, v1;
            v0.x = acc[i][j][0] + bx;  v0.y = acc[i][j][1] + by;
            v1.x = acc[i][j][2] + bx;  v1.y = acc[i][j][3] + by;
            if (OP == 1) {
                v0.x = fmaxf(v0.x, 0.0f); v0.y = fmaxf(v0.y, 0.0f);
                v1.x = fmaxf(v1.x, 0.0f); v1.y = fmaxf(v1.y, 0.0f);
            }
            if (OUTM & 1) {
                *(float2*)(C + (size_t)r0 * N + c) = v0;
                *(float2*)(C + (size_t)(r0 + 8) * N + c) = v1;
            }
            if (OUTM & 2) {
                *(unsigned*)(Cb + (size_t)r0 * N + c) = pk2(v0.x, v0.y);
                *(unsigned*)(Cb + (size_t)(r0 + 8) * N + c) = pk2(v1.x, v1.y);
            }
        }
    }
}

// ---------------------------------------------------------------------------
// Fused GEMM(+bias+residual)+LayerNorm for N=256 GEMMs (wo, ff2).
// BM=32 x 256 tile -> grid 192 blocks (full wave).  8 warps along N
// (warp tile 32x32).  LN computed in epilogue via redS/redQ[32][8].
// DO_LN=1: writes x (fp32) and xn = LN(x) (bf16).
// DO_LN=0: writes x (fp32) and xb = bf16(x).
// ---------------------------------------------------------------------------
template<int DO_LN>
__global__ __launch_bounds__(256, 2)
void g32ln_k(const bf16* __restrict__ A, const bf16* __restrict__ B,
             const float* __restrict__ bias, const float* __restrict__ res,
             float* __restrict__ C, bf16* __restrict__ Cb,
             const float* __restrict__ lns, const float* __restrict__ lnb,
             int K)
{
    constexpr int N = 256;
    __shared__ bf16 As[4][32][24];
    __shared__ bf16 Bs[4][16][264];
    __shared__ float redS[32][8];
    __shared__ float redQ[32][8];

    int tid  = threadIdx.x;
    int lane = tid & 31, wid = tid >> 5;
    int g = lane >> 2, lt = lane & 3;
    int wn = wid * 32;               // 8 warps along N
    int m0 = blockIdx.x * 32;

    int ltile = lane >> 3, lr = lane & 7;
    int a_roff = (ltile & 1) * 8 + lr;
    int a_koff = (ltile >> 1) * 8;
    int b_roff = (ltile & 1) * 8 + lr;
    int b_coff = (ltile >> 1) * 8;

    float acc[2][4][4];
    #pragma unroll
    for (int i = 0; i < 2; i++)
        #pragma unroll
        for (int j = 0; j < 4; j++)
            #pragma unroll
            for (int v = 0; v < 4; v++) acc[i][j][v] = 0.0f;

    int T = K >> 4;

    auto issue = [&](int buf, int kt) {
        int k0 = kt * 16;
        if (tid < 64)
            cpa16(&As[buf][tid >> 1][(tid & 1) * 8],
                  A + (size_t)(m0 + (tid >> 1)) * K + k0 + (tid & 1) * 8);
        #pragma unroll
        for (int jj = 0; jj < 2; jj++) {
            int idx = tid + jj * 256;
            int br = idx >> 5, bc = (idx & 31) * 8;
            cpa16(&Bs[buf][br][bc], B + (size_t)(k0 + br) * N + bc);
        }
    };

    issue(0, 0); cpa_commit();
    issue(1, 1); cpa_commit();
    issue(2, 2); cpa_commit();

    for (int kt = 0; kt < T; kt++) {
        cpa_wait2();
        __syncthreads();
        if (kt + 3 < T) issue((kt + 3) & 3, kt + 3);
        cpa_commit();

        int buf = kt & 3;
        unsigned af[2][4], bf[4][2];
        #pragma unroll
        for (int i = 0; i < 2; i++)
            ldsm4(af[i][0], af[i][1], af[i][2], af[i][3],
                  &As[buf][16 * i + a_roff][a_koff]);
        #pragma unroll
        for (int jp = 0; jp < 2; jp++) {
            unsigned r0, r1, r2, r3;
            ldsm4t(r0, r1, r2, r3, &Bs[buf][b_roff][wn + 16 * jp + b_coff]);
            bf[2 * jp][0] = r0;  bf[2 * jp][1] = r1;
            bf[2 * jp + 1][0] = r2;  bf[2 * jp + 1][1] = r3;
        }
        #pragma unroll
        for (int i = 0; i < 2; i++)
            #pragma unroll
            for (int j = 0; j < 4; j++)
                mma_bf16(acc[i][j], af[i][0], af[i][1], af[i][2], af[i][3],
                         bf[j][0], bf[j][1]);
    }

    // ---- epilogue: bias + residual -> x; then LN (or bf16 copy) ----
    float vals[4][8];     // rr = 2i + h -> local row 16i + 8h + g; 8 cols
    #pragma unroll
    for (int i = 0; i < 2; i++) {
        int rA = m0 + 16 * i + g;
        #pragma unroll
        for (int j = 0; j < 4; j++) {
            int c = wn + 8 * j + 2 * lt;
            float bx = bias[c], by = bias[c + 1];
            float2 rv0 = *(const float2*)(res + (size_t)rA * N + c);
            float2 rv1 = *(const float2*)(res + (size_t)(rA + 8) * N + c);
            float v0x = acc[i][j][0] + bx + rv0.x;
            float v0y = acc[i][j][1] + by + rv0.y;
            float v1x = acc[i][j][2] + bx + rv1.x;
            float v1y = acc[i][j][3] + by + rv1.y;
            vals[2 * i][2 * j]     = v0x;  vals[2 * i][2 * j + 1]     = v0y;
            vals[2 * i + 1][2 * j] = v1x;  vals[2 * i + 1][2 * j + 1] = v1y;
            float2 w0; w0.x = v0x; w0.y = v0y;
            float2 w1; w1.x = v1x; w1.y = v1y;
            *(float2*)(C + (size_t)rA * N + c) = w0;
            *(float2*)(C + (size_t)(rA + 8) * N + c) = w1;
        }
    }

    if (DO_LN) {
        #pragma unroll
        for (int rr = 0; rr < 4; rr++) {
            float s = 0.0f, q = 0.0f;
            #pragma unroll
            for (int t = 0; t < 8; t++) { s += vals[rr][t]; q += vals[rr][t] * vals[rr][t]; }
            #pragma unroll
            for (int off = 1; off <= 2; off <<= 1) {
                s += __shfl_xor_sync(0xffffffffu, s, off);
                q += __shfl_xor_sync(0xffffffffu, q, off);
            }
            if (lt == 0) {
                int lrow = 16 * (rr >> 1) + 8 * (rr & 1) + g;
                redS[lrow][wid] = s;
                redQ[lrow][wid] = q;
            }
        }
        __syncthreads();
        #pragma unroll
        for (int rr = 0; rr < 4; rr++) {
            int lrow = 16 * (rr >> 1) + 8 * (rr & 1) + g;
            float S = 0.0f, Q = 0.0f;
            #pragma unroll
            for (int w2 = 0; w2 < 8; w2++) { S += redS[lrow][w2]; Q += redQ[lrow][w2]; }
            float mu = S * (1.0f / 256.0f);
            float var = Q * (1.0f / 256.0f) - mu * mu;
            float rs = rsqrtf(var + 1e-5f);
            int row = m0 + lrow;
            #pragma unroll
            for (int j = 0; j < 4; j++) {
                int c = wn + 8 * j + 2 * lt;
                float x0 = (vals[rr][2 * j]     - mu) * rs * lns[c]     + lnb[c];
                float x1 = (vals[rr][2 * j + 1] - mu) * rs * lns[c + 1] + lnb[c + 1];
                *(unsigned*)(Cb + (size_t)row * N + c) = pk2(x0, x1);
            }
        }
    } else {
        #pragma unroll
        for (int rr = 0; rr < 4; rr++) {
            int row = m0 + 16 * (rr >> 1) + 8 * (rr & 1) + g;
            #pragma unroll
            for (int j = 0; j < 4; j++) {
                int c = wn + 8 * j + 2 * lt;
                *(unsigned*)(Cb + (size_t)row * N + c)
                    = pk2(vals[rr][2 * j], vals[rr][2 * j + 1]);
            }
        }
    }
}

// ---------------------------------------------------------------------------
// In-place log_softmax over VOCAB=1024
// ---------------------------------------------------------------------------
__global__ void lsm_k(float* __restrict__ out)
{
    __shared__ float red[256];
    int n = blockIdx.x, t = threadIdx.x;
    float v[4];
    #pragma unroll
    for (int j = 0; j < 4; j++) v[j] = out[(size_t)n * NVOCAB + t + j * 256];

    float m = fmaxf(fmaxf(v[0], v[1]), fmaxf(v[2], v[3]));
    red[t] = m;
    __syncthreads();
    #pragma unroll
    for (int o = 128; o > 0; o >>= 1) {
        if (t < o) red[t] = fmaxf(red[t], red[t + o]);
        __syncthreads();
    }
    float M = red[0];
    __syncthreads();

    float s = 0.0f;
    #pragma unroll
    for (int j = 0; j < 4; j++) s += __expf(v[j] - M);
    red[t] = s;
    __syncthreads();
    #pragma unroll
    for (int o = 128; o > 0; o >>= 1) {
        if (t < o) red[t] += red[t + o];
        __syncthreads();
    }
    float lse = M + __logf(red[0]);

    #pragma unroll
    for (int j = 0; j < 4; j++)
        out[(size_t)n * NVOCAB + t + j * 256] = v[j] - lse;
}

// ---------------------------------------------------------------------------
// Launch
// ---------------------------------------------------------------------------
extern "C" void kernel_launch(void* const* d_in, const int* in_sizes, int n_in,
                              void* d_out, int out_size)
{
    const int*   tokens    = (const int*)  d_in[0];
    const int*   pos_idx   = (const int*)  d_in[1];
    const float* value_emb = (const float*)d_in[4];
    const float* coord_emb = (const float*)d_in[5];
    const float* pos_emb   = (const float*)d_in[6];
    const float* ln1_s     = (const float*)d_in[7];
    const float* ln1_b     = (const float*)d_in[8];
    const float* W_qkv     = (const float*)d_in[9];
    const float* b_qkv     = (const float*)d_in[10];
    const float* W_o       = (const float*)d_in[11];
    const float* b_o       = (const float*)d_in[12];
    const float* ln2_s     = (const float*)d_in[13];
    const float* ln2_b     = (const float*)d_in[14];
    const float* W_ff1     = (const float*)d_in[15];
    const float* b_ff1     = (const float*)d_in[16];
    const float* W_ff2     = (const float*)d_in[17];
    const float* b_ff2     = (const float*)d_in[18];
    const float* W_gen     = (const float*)d_in[19];
    const float* b_gen     = (const float*)d_in[20];
    float* out = (float*)d_out;

    float *x;
    bf16 *qkvb, *xn, *att, *mid, *xb;
    bf16 *wqkvb, *wob, *wf1b, *wf2b, *wgenb;
    cudaGetSymbolAddress((void**)&x,    g_x);
    cudaGetSymbolAddress((void**)&qkvb, g_qkvb);
    cudaGetSymbolAddress((void**)&xn,   g_xn);
    cudaGetSymbolAddress((void**)&att,  g_att);
    cudaGetSymbolAddress((void**)&mid,  g_mid);
    cudaGetSymbolAddress((void**)&xb,   g_xb);
    cudaGetSymbolAddress((void**)&wqkvb, g_wqkv);
    cudaGetSymbolAddress((void**)&wob,   g_wo);
    cudaGetSymbolAddress((void**)&wf1b,  g_wf1);
    cudaGetSymbolAddress((void**)&wf2b,  g_wf2);
    cudaGetSymbolAddress((void**)&wgenb, g_wgen);

    cvt5_k<<<1792, 256>>>((const float4*)W_qkv, (const float4*)W_o,
                          (const float4*)W_ff1, (const float4*)W_ff2,
                          (const float4*)W_gen,
                          (uint2*)wqkvb, (uint2*)wob, (uint2*)wf1b,
                          (uint2*)wf2b, (uint2*)wgenb);

    embed_k<<<NTOK, DMODEL>>>(tokens, pos_idx, value_emb, coord_emb, pos_emb, x);

    // layer-0 ln1 (subsequent ln1/ln2 are fused into GEMM epilogues)
    ln_k<<<NTOK / 8, 256>>>(x, ln1_s, ln1_b, xn);

    for (int l = 0; l < NLAYER; l++) {
        const bf16* wqkv = wqkvb + (size_t)l * DMODEL * 3 * DMODEL;
        const float* bqkv = b_qkv + (size_t)l * 3 * DMODEL;
        const bf16* wo    = wob   + (size_t)l * DMODEL * DMODEL;
        const float* bo   = b_o   + (size_t)l * DMODEL;
        const bf16* wf1   = wf1b  + (size_t)l * DMODEL * 4 * DMODEL;
        const float* bf1  = b_ff1 + (size_t)l * 4 * DMODEL;
        const bf16* wf2   = wf2b  + (size_t)l * 4 * DMODEL * DMODEL;
        const float* bf2  = b_ff2 + (size_t)l * DMODEL;

        { dim3 g(3 * DMODEL / 128, NTOK / 128);
          hg128_k<0, 2><<<g, 256>>>(xn, wqkv, bqkv, nullptr, qkvb,
                                    NTOK, 3 * DMODEL, DMODEL); }

        attn_k<<<NBATCH * NHEAD, 128>>>(qkvb, att);

        // wo GEMM + residual + ln2 fused
        g32ln_k<1><<<NTOK / 32, 256>>>(att, wo, bo, x, x, xn,
                                       ln2_s + l * DMODEL, ln2_b + l * DMODEL, 256);

        { dim3 g(4 * DMODEL / 128, NTOK / 128);
          hg128_k<1, 2><<<g, 256>>>(xn, wf1, bf1, nullptr, mid,
                                    NTOK, 4 * DMODEL, DMODEL); }

        // ff2 GEMM + residual, fused with next layer's ln1 (or xb for generator)
        if (l + 1 < NLAYER) {
            g32ln_k<1><<<NTOK / 32, 256>>>(mid, wf2, bf2, x, x, xn,
                                           ln1_s + (l + 1) * DMODEL,
                                           ln1_b + (l + 1) * DMODEL, 1024);
        } else {
            g32ln_k<0><<<NTOK / 32, 256>>>(mid, wf2, bf2, x, x, xb,
                                           nullptr, nullptr, 1024);
        }
    }

    { dim3 g(NVOCAB / 128, NTOK / 128);
      hg128_k<0, 1><<<g, 256>>>(xb, wgenb, b_gen, out, nullptr,
                                NTOK, NVOCAB, DMODEL); }

    lsm_k<<<NTOK, 256>>>(out);
}